// round 17
// baseline (speedup 1.0000x reference)
#include <cuda_runtime.h>
#include <cstdint>

// ============================================================================
// ForexLSTM: 2-layer LSTM (B=512, T=1024, H=65) + final linear.
//
// R17: interleaved-phase recurrence. CTA = 4 rows = two sets {0,1},{2,3}.
//  Each phase: 520 matvec threads (1 gate x 1 row of current set) run
//  CONCURRENTLY with 130 eltwise threads finishing the OTHER set's previous
//  step. One barrier per phase, 2 phases per step — same barrier count as
//  before but no eltwise-only dead phase. 672 threads, 1 CTA/SM, ~21 warps.
//  pre_kernel: proven 8-row double-buffered version (676us). 
// ============================================================================

using u32 = unsigned int;
using ull = unsigned long long;

constexpr int B = 512, T = 1024, H = 65, G4 = 260;
constexpr int PTHR = 288, PGRID = 296;
constexpr int TILE = 8;
constexpr int NTILES = (B * T) / TILE;        // 65536
constexpr int RTHR = 672, RGRID = 128;        // 4 rows per CTA

__device__ float g_pre[(size_t)B * T * G4];   // pre-activations (both layers)
__device__ float g_h1 [(size_t)B * T * H];    // layer-0 output sequence
__device__ float g_hN [B * H];                // layer-1 last-step h

// ---------------- helpers ----------------
__device__ __forceinline__ ull pack2(float x, float y) {
    ull r; asm("mov.b64 %0, {%1, %2};" : "=l"(r) : "f"(x), "f"(y)); return r;
}
__device__ __forceinline__ float2 unpack2(ull v) {
    float2 r; asm("mov.b64 {%0, %1}, %2;" : "=f"(r.x), "=f"(r.y) : "l"(v)); return r;
}
__device__ __forceinline__ void fma2(ull& d, ull a, ull b) {
    asm("fma.rn.f32x2 %0, %1, %2, %0;" : "+l"(d) : "l"(a), "l"(b));
}
__device__ __forceinline__ void lds128(ull& a, ull& b, u32 addr) {
    asm volatile("ld.shared.v2.u64 {%0, %1}, [%2];" : "=l"(a), "=l"(b) : "r"(addr));
}
__device__ __forceinline__ ull lds64(u32 addr) {
    ull a; asm volatile("ld.shared.u64 %0, [%1];" : "=l"(a) : "r"(addr)); return a;
}
__device__ __forceinline__ float lds32(u32 addr) {
    float v; asm volatile("ld.shared.f32 %0, [%1];" : "=f"(v) : "r"(addr)); return v;
}
__device__ __forceinline__ void sts32(u32 addr, float v) {
    asm volatile("st.shared.f32 [%0], %1;" :: "r"(addr), "f"(v) : "memory");
}
__device__ __forceinline__ float fast_sigmoid(float v) {
    return __fdividef(1.0f, 1.0f + __expf(-v));
}
__device__ __forceinline__ float fast_tanh(float v) {
    return 1.0f - 2.0f * __fdividef(1.0f, __expf(2.0f * v) + 1.0f);
}

// ============================================================================
// pre[row, g] = (b_ih[g]+b_hh[g]) + sum_i xin[row,i] * w_ih[g,i]
// 8-row double-buffered tiles; one __syncthreads per tile. (R7 proven)
// ============================================================================
__global__ void __launch_bounds__(PTHR, 2)
pre_kernel(const float* __restrict__ x_ext,
           const float* __restrict__ w_ih,
           const float* __restrict__ b_ih,
           const float* __restrict__ b_hh,
           int layer)
{
    const float* xin = (layer == 0) ? x_ext : g_h1;

    __shared__ __align__(16) float xs[2][TILE * 68];
    const int tid = threadIdx.x;
    const bool act = tid < G4;

    ull wih[33]; float bg = 0.f;
    if (act) {
        const float* wi = w_ih + tid * H;
#pragma unroll
        for (int j = 0; j < 32; j++)
            wih[j] = pack2(__ldg(wi + 2 * j), __ldg(wi + 2 * j + 1));
        wih[32] = pack2(__ldg(wi + 64), 0.f);
        bg = __ldg(b_ih + tid) + __ldg(b_hh + tid);
    }
    for (int k = tid; k < 2 * TILE * 68; k += PTHR) (&xs[0][0])[k] = 0.f;
    __syncthreads();

    const int f0 = tid, f1 = tid + 260;
    const int s0 = (f0 / 65) * 68 + (f0 % 65);
    const int s1 = (f1 / 65) * 68 + (f1 % 65);

    int gi = blockIdx.x;
    if (act) {
        const float* src = xin + (size_t)gi * (TILE * H);
        xs[0][s0] = __ldg(src + f0);
        xs[0][s1] = __ldg(src + f1);
    }
    __syncthreads();

    const u32 xb = (u32)__cvta_generic_to_shared(&xs[0][0]);
    int cur = 0;
    for (; gi < NTILES; gi += PGRID) {
        const int gn = gi + PGRID;
        float xn0 = 0.f, xn1 = 0.f;
        if (act && gn < NTILES) {
            const float* src = xin + (size_t)gn * (TILE * H);
            xn0 = __ldg(src + f0);
            xn1 = __ldg(src + f1);
        }

        if (act) {
            const u32 bT = xb + cur * (TILE * 68 * 4);
#pragma unroll
            for (int sb = 0; sb < 2; sb++) {
                ull a0 = pack2(bg, 0.f), a1 = a0, a2 = a0, a3 = a0;
                const u32 bA = bT + sb * (4 * 272);
#pragma unroll
                for (int q = 0; q < 16; q++) {
                    ull u0, u1;
                    lds128(u0, u1, bA + 0 * 272 + q * 16);
                    fma2(a0, wih[2 * q], u0); fma2(a0, wih[2 * q + 1], u1);
                    lds128(u0, u1, bA + 1 * 272 + q * 16);
                    fma2(a1, wih[2 * q], u0); fma2(a1, wih[2 * q + 1], u1);
                    lds128(u0, u1, bA + 2 * 272 + q * 16);
                    fma2(a2, wih[2 * q], u0); fma2(a2, wih[2 * q + 1], u1);
                    lds128(u0, u1, bA + 3 * 272 + q * 16);
                    fma2(a3, wih[2 * q], u0); fma2(a3, wih[2 * q + 1], u1);
                }
                fma2(a0, wih[32], lds64(bA + 0 * 272 + 256));
                fma2(a1, wih[32], lds64(bA + 1 * 272 + 256));
                fma2(a2, wih[32], lds64(bA + 2 * 272 + 256));
                fma2(a3, wih[32], lds64(bA + 3 * 272 + 256));

                float* op = g_pre + ((size_t)gi * TILE + sb * 4) * G4 + tid;
                float2 s;
                s = unpack2(a0); op[0]      = s.x + s.y;
                s = unpack2(a1); op[G4]     = s.x + s.y;
                s = unpack2(a2); op[2 * G4] = s.x + s.y;
                s = unpack2(a3); op[3 * G4] = s.x + s.y;
            }
        }
        if (act && gn < NTILES) {
            xs[cur ^ 1][s0] = xn0;
            xs[cur ^ 1][s1] = xn1;
        }
        __syncthreads();
        cur ^= 1;
    }
}

// ============================================================================
// Interleaved-phase recurrent kernel. 128 CTAs x 4 rows (sets A={0,1},B={2,3}).
// 672 threads: tid<520 matvec (rs=tid/260 row-in-set, g=tid%260);
//              tid in [520,650) eltwise (re=(tid-520)/65, j=(tid-520)%65).
// Phase 2t  : matvec A@t  || eltwise B@(t-1)
// Phase 2t+1: matvec B@t  || eltwise A@t
// Final     : eltwise B@(T-1)
// ============================================================================
__global__ void __launch_bounds__(RTHR, 1)
recur_kernel(const float* __restrict__ w_hh, int write_all)
{
    __shared__ __align__(16) float h_sm[4 * 68];          // rows 0..3
    __shared__ __align__(16) float gates_sm[2][2 * G4];   // [set][rs*260+g]

    const int tid = threadIdx.x;
    const int b0  = blockIdx.x * 4;
    const bool mv = tid < 520;
    const int rs = mv ? (tid / G4) : 0;       // row within set
    const int g  = mv ? (tid % G4) : 0;

    const int et = tid - 520;
    const bool ew = (et >= 0) && (et < 130);
    const int re = ew ? (et / 65) : 0;
    const int j  = ew ? (et % 65) : 0;

    // ---- matvec thread state ----
    ull whh[33];
    if (mv) {
        const float* wr = w_hh + g * H;
#pragma unroll
        for (int q = 0; q < 32; q++)
            whh[q] = pack2(__ldg(wr + 2 * q), __ldg(wr + 2 * q + 1));
        whh[32] = pack2(__ldg(wr + 64), 0.f);
    }
    const float* ppA = g_pre + ((size_t)(b0 + rs)     * T) * G4 + g;
    const float* ppB = g_pre + ((size_t)(b0 + 2 + rs) * T) * G4 + g;
    float pvA = 0.f, pvB = 0.f;
    if (mv) {
        pvA = __ldg(ppA); ppA += G4;
        pvB = __ldg(ppB); ppB += G4;
    }

    // ---- eltwise thread state ----
    float c0 = 0.f, c1 = 0.f;   // cell state: set A row re / set B row re
    float* oA = write_all ? g_h1 + ((size_t)(b0 + re)     * T) * H + j
                          : g_hN + (size_t)(b0 + re) * H + j;
    float* oB = write_all ? g_h1 + ((size_t)(b0 + 2 + re) * T) * H + j
                          : g_hN + (size_t)(b0 + 2 + re) * H + j;

    for (int k = tid; k < 4 * 68; k += RTHR) h_sm[k] = 0.f;
    __syncthreads();

    const u32 hb = (u32)__cvta_generic_to_shared(h_sm);
    const u32 gb = (u32)__cvta_generic_to_shared(&gates_sm[0][0]);

    // matvec for one set (compile-time SET), raw gate -> gates_sm[SET]
    #define MATVEC(SET, PV)                                                     \
    {                                                                           \
        const u32 hr = hb + ((SET) * 2 + rs) * 272;                             \
        ull a0 = 0ull, a1 = 0ull;                                               \
        _Pragma("unroll")                                                       \
        for (int q = 0; q < 8; q++) {                                           \
            ull u0, u1, u2, u3;                                                 \
            lds128(u0, u1, hr + q * 32);                                        \
            lds128(u2, u3, hr + q * 32 + 16);                                   \
            fma2(a0, whh[4 * q],     u0); fma2(a1, whh[4 * q + 1], u1);         \
            fma2(a0, whh[4 * q + 2], u2); fma2(a1, whh[4 * q + 3], u3);         \
        }                                                                       \
        fma2(a0, whh[32], lds64(hr + 256));                                     \
        float2 s0 = unpack2(a0), s1 = unpack2(a1);                              \
        float v = ((s0.x + s0.y) + (s1.x + s1.y)) + (PV);                       \
        sts32(gb + (SET) * (2 * G4 * 4) + (rs * G4 + g) * 4, v);                \
    }

    // eltwise for one set at step te (writes h_sm + output, updates C)
    #define ELTWISE(SET, C, OPTR, TE)                                           \
    {                                                                           \
        const u32 ga = gb + (SET) * (2 * G4 * 4) + re * (G4 * 4) + j * 4;       \
        float vi = lds32(ga);                                                   \
        float vf = lds32(ga + 65 * 4);                                          \
        float vg = lds32(ga + 130 * 4);                                         \
        float vo = lds32(ga + 195 * 4);                                         \
        float iv = fast_sigmoid(vi);                                            \
        float fv = fast_sigmoid(vf);                                            \
        float gv = fast_tanh(vg);                                               \
        float ov = fast_sigmoid(vo);                                            \
        (C) = fv * (C) + iv * gv;                                               \
        float hv = ov * fast_tanh(C);                                           \
        h_sm[((SET) * 2 + re) * 68 + j] = hv;                                   \
        if (write_all)             (OPTR)[(size_t)(TE) * H] = hv;               \
        else if ((TE) == T - 1)    (OPTR)[0] = hv;                              \
    }

    for (int t = 0; t < T; t++) {
        // ---- phase 2t: matvec A@t || eltwise B@(t-1) ----
        if (mv) {
            float pvv = pvA;
            if (t + 1 < T) { pvA = __ldg(ppA); ppA += G4; }
            MATVEC(0, pvv);
        }
        if (ew && t >= 1) ELTWISE(1, c1, oB, t - 1);
        __syncthreads();

        // ---- phase 2t+1: matvec B@t || eltwise A@t ----
        if (mv) {
            float pvv = pvB;
            if (t + 1 < T) { pvB = __ldg(ppB); ppB += G4; }
            MATVEC(1, pvv);
        }
        if (ew) ELTWISE(0, c0, oA, t);
        __syncthreads();
    }
    // ---- final phase: eltwise B@(T-1) ----
    if (ew) ELTWISE(1, c1, oB, T - 1);

    #undef MATVEC
    #undef ELTWISE
}

// ============================================================================
// out[b] = g_hN[b,:] . w_lin + b_lin
// ============================================================================
__global__ void final_linear_kernel(const float* __restrict__ w_lin,
                                    const float* __restrict__ b_lin,
                                    float* __restrict__ out)
{
    __shared__ float w[72];
    const int tid = threadIdx.x;
    if (tid < H) w[tid] = __ldg(w_lin + tid);
    __syncthreads();
    const int b = blockIdx.x * blockDim.x + tid;
    if (b < B) {
        const float* h = g_hN + (size_t)b * H;
        float s = __ldg(b_lin);
#pragma unroll
        for (int i = 0; i < H; i++) s += h[i] * w[i];
        out[b] = s;
    }
}

// ============================================================================
extern "C" void kernel_launch(void* const* d_in, const int* in_sizes, int n_in,
                              void* d_out, int out_size)
{
    const float* x     = (const float*)d_in[0];
    const float* w_ih0 = (const float*)d_in[1];
    const float* w_hh0 = (const float*)d_in[2];
    const float* b_ih0 = (const float*)d_in[3];
    const float* b_hh0 = (const float*)d_in[4];
    const float* w_ih1 = (const float*)d_in[5];
    const float* w_hh1 = (const float*)d_in[6];
    const float* b_ih1 = (const float*)d_in[7];
    const float* b_hh1 = (const float*)d_in[8];
    const float* w_lin = (const float*)d_in[9];
    const float* b_lin = (const float*)d_in[10];

    pre_kernel<<<PGRID, PTHR>>>(x, w_ih0, b_ih0, b_hh0, 0);
    recur_kernel<<<RGRID, RTHR>>>(w_hh0, 1);
    pre_kernel<<<PGRID, PTHR>>>(x, w_ih1, b_ih1, b_hh1, 1);
    recur_kernel<<<RGRID, RTHR>>>(w_hh1, 0);
    final_linear_kernel<<<2, 256>>>(w_lin, b_lin, (float*)d_out);
}